// round 8
// baseline (speedup 1.0000x reference)
#include <cuda_runtime.h>
#include <stdint.h>

#define NMAX 50000
#define EMAX 600000
#define SCAN_BLK 2048
#define MAX_SBLK 32

typedef unsigned long long ull;

// ---------------- CSR scratch ----------------
__device__ int g_rowptr[3][NMAX + 1];
__device__ int g_cursor[3][NMAX];
__device__ int g_esrc[3][EMAX];
__device__ int g_bsum[3][MAX_SBLK];
__device__ int g_boff[3][MAX_SBLK];
__device__ int g_total[3];

// ---------------- float scratch (only layer-2 transformed features) ----------------
constexpr size_t F_T_DDI = 0;                                  // [ND,64]
constexpr size_t F_T_DPI = F_T_DDI + (size_t)NMAX * 64;
constexpr size_t F_T_PPI = F_T_DPI + (size_t)NMAX * 64;
constexpr size_t F_TOTAL = F_T_PPI + (size_t)NMAX * 64;

__device__ float g_fs[F_TOTAL];

// ---------------- packed f32x2 helpers ----------------
__device__ __forceinline__ ull ffma2(ull a, ull b, ull c) {
    ull d;
    asm("fma.rn.f32x2 %0, %1, %2, %3;" : "=l"(d) : "l"(a), "l"(b), "l"(c));
    return d;
}
__device__ __forceinline__ ull pack2(float lo, float hi) {
    ull d;
    asm("mov.b64 %0, {%1, %2};" : "=l"(d) : "f"(lo), "f"(hi));
    return d;
}
__device__ __forceinline__ void unpack2(ull v, float& lo, float& hi) {
    asm("mov.b64 {%0, %1}, %2;" : "=f"(lo), "=f"(hi) : "l"(v));
}

// ---------------- CSR build ----------------

__global__ void k_zero_counts() {
    int i = blockIdx.x * blockDim.x + threadIdx.x;
    int total = 3 * (NMAX + 1);
    int stride = gridDim.x * blockDim.x;
    int* p = &g_rowptr[0][0];
    for (; i < total; i += stride) p[i] = 0;
}

__global__ void k_count(const int* __restrict__ d0, int e0,
                        const int* __restrict__ d1, int e1,
                        const int* __restrict__ d2, int e2) {
    int i = blockIdx.x * blockDim.x + threadIdx.x;
    int stride = gridDim.x * blockDim.x;
    for (int j = i; j < e0; j += stride) atomicAdd(&g_rowptr[0][__ldg(d0 + j)], 1);
    for (int j = i; j < e1; j += stride) atomicAdd(&g_rowptr[1][__ldg(d1 + j)], 1);
    for (int j = i; j < e2; j += stride) atomicAdd(&g_rowptr[2][__ldg(d2 + j)], 1);
}

__global__ void __launch_bounds__(1024)
k_scan1(int sblk, int n0, int n1, int n2) {
    __shared__ int sh[1024];
    int rel = blockIdx.x / sblk;
    int blk = blockIdx.x % sblk;
    int n = (rel == 0) ? n0 : ((rel == 1) ? n1 : n2);
    int* cnt = g_rowptr[rel];
    int tid = threadIdx.x;
    int base = blk * SCAN_BLK + tid * 2;
    int c0 = (base < n)     ? cnt[base]     : 0;
    int c1 = (base + 1 < n) ? cnt[base + 1] : 0;
    sh[tid] = c0 + c1;
    __syncthreads();
    for (int off = 1; off < 1024; off <<= 1) {
        int v = (tid >= off) ? sh[tid - off] : 0;
        __syncthreads();
        sh[tid] += v;
        __syncthreads();
    }
    int toff = (tid > 0) ? sh[tid - 1] : 0;
    if (base < n)     cnt[base]     = toff;
    if (base + 1 < n) cnt[base + 1] = toff + c0;
    if (tid == 1023) g_bsum[rel][blk] = sh[1023];
}

__global__ void k_scan2(int sblk) {
    int rel = threadIdx.x >> 5;
    int lane = threadIdx.x & 31;
    if (rel >= 3) return;
    int v = (lane < sblk) ? g_bsum[rel][lane] : 0;
    int orig = v;
#pragma unroll
    for (int off = 1; off < 32; off <<= 1) {
        int u = __shfl_up_sync(0xFFFFFFFF, v, off);
        if (lane >= off) v += u;
    }
    if (lane < sblk) g_boff[rel][lane] = v - orig;
    if (lane == 31) g_total[rel] = v;
}

__global__ void k_scan3(int sblk, int n0, int n1, int n2) {
    int i = blockIdx.x * blockDim.x + threadIdx.x;
    int stride = gridDim.x * blockDim.x;
    int total = 3 * NMAX;
    for (int t = i; t < total; t += stride) {
        int rel = t / NMAX;
        int idx = t % NMAX;
        int n = (rel == 0) ? n0 : ((rel == 1) ? n1 : n2);
        if (idx < n) {
            int v = g_rowptr[rel][idx] + g_boff[rel][idx / SCAN_BLK];
            g_rowptr[rel][idx] = v;
            g_cursor[rel][idx] = v;
        }
        if (idx == 0) g_rowptr[rel][n] = g_total[rel];
    }
}

__global__ void k_fill3(const int* __restrict__ s0, const int* __restrict__ d0, int e0,
                        const int* __restrict__ s1, const int* __restrict__ d1, int e1,
                        const int* __restrict__ s2, const int* __restrict__ d2, int e2) {
    int i = blockIdx.x * blockDim.x + threadIdx.x;
    int stride = gridDim.x * blockDim.x;
    for (int e = i; e < e0; e += stride) {
        int pos = atomicAdd(&g_cursor[0][__ldg(d0 + e)], 1);
        g_esrc[0][pos] = __ldg(s0 + e);
    }
    for (int e = i; e < e1; e += stride) {
        int pos = atomicAdd(&g_cursor[1][__ldg(d1 + e)], 1);
        g_esrc[1][pos] = __ldg(s1 + e);
    }
    for (int e = i; e < e2; e += stride) {
        int pos = atomicAdd(&g_cursor[2][__ldg(d2 + e)], 1);
        g_esrc[2][pos] = __ldg(s2 + e);
    }
}

// ---------------- gather primitives ----------------

__device__ __forceinline__ void node_range(const int* __restrict__ ptr, int node, int n,
                                           int& b, int& d) {
    if (node < n) {
        b = ptr[node];
        d = ptr[node + 1] - b;
    } else {
        b = 0; d = 0;
    }
}

// Pair-interleaved 128-dim gather: 2 nodes/warp, unroll-4 -> 8 loads in flight.
__device__ __forceinline__ void gpair128(const int* __restrict__ es,
                                         const float* __restrict__ x,
                                         int b0, int d0, int b1, int d1, int lane,
                                         float4& o0, float4& o1) {
    float4 a0 = make_float4(0.f, 0.f, 0.f, 0.f);
    float4 a1 = make_float4(0.f, 0.f, 0.f, 0.f);
    int m = d0 > d1 ? d0 : d1;
    for (int e = 0; e < m; e += 4) {
        float4 v0[4], v1[4];
#pragma unroll
        for (int j = 0; j < 4; j++) {
            bool q0 = (e + j) < d0;
            bool q1 = (e + j) < d1;
            int s0 = q0 ? __ldg(es + b0 + e + j) : 0;
            int s1 = q1 ? __ldg(es + b1 + e + j) : 0;
            v0[j] = q0 ? __ldg(reinterpret_cast<const float4*>(x + (size_t)s0 * 128) + lane)
                       : make_float4(0.f, 0.f, 0.f, 0.f);
            v1[j] = q1 ? __ldg(reinterpret_cast<const float4*>(x + (size_t)s1 * 128) + lane)
                       : make_float4(0.f, 0.f, 0.f, 0.f);
        }
#pragma unroll
        for (int j = 0; j < 4; j++) {
            a0.x += v0[j].x; a0.y += v0[j].y; a0.z += v0[j].z; a0.w += v0[j].w;
            a1.x += v1[j].x; a1.y += v1[j].y; a1.z += v1[j].z; a1.w += v1[j].w;
        }
    }
    float i0 = 1.0f / fmaxf((float)d0, 1.0f);
    float i1 = 1.0f / fmaxf((float)d1, 1.0f);
    o0 = make_float4(a0.x * i0, a0.y * i0, a0.z * i0, a0.w * i0);
    o1 = make_float4(a1.x * i1, a1.y * i1, a1.z * i1, a1.w * i1);
}

// Quad-interleaved 64-dim gather: 4 nodes/warp, unroll-2 -> 8 loads in flight.
__device__ __forceinline__ void gquad64(const int* __restrict__ es,
                                        const float* __restrict__ x,
                                        const int* b, const int* d, int lane,
                                        float2* out) {
    float2 a[4];
#pragma unroll
    for (int q = 0; q < 4; q++) a[q] = make_float2(0.f, 0.f);
    int m = d[0];
    if (d[1] > m) m = d[1];
    if (d[2] > m) m = d[2];
    if (d[3] > m) m = d[3];
    for (int e = 0; e < m; e += 2) {
        float2 v[8];
#pragma unroll
        for (int q = 0; q < 4; q++) {
#pragma unroll
            for (int j = 0; j < 2; j++) {
                bool p = (e + j) < d[q];
                int s = p ? __ldg(es + b[q] + e + j) : 0;
                v[q * 2 + j] = p ? __ldg(reinterpret_cast<const float2*>(x + (size_t)s * 64) + lane)
                                 : make_float2(0.f, 0.f);
            }
        }
#pragma unroll
        for (int q = 0; q < 4; q++) {
            a[q].x += v[q * 2].x + v[q * 2 + 1].x;
            a[q].y += v[q * 2].y + v[q * 2 + 1].y;
        }
    }
#pragma unroll
    for (int q = 0; q < 4; q++) {
        float inv = 1.0f / fmaxf((float)d[q], 1.0f);
        out[q] = make_float2(a[q].x * inv, a[q].y * inv);
    }
}

// ---------------- fused layer-1 gather + GEMM1 + GEMM2 ----------------
// 256 threads, 16 dst rows/block.
// Phase G: warp w gathers nodes row0+2w, row0+2w+1 into xs (k-paired float2).
// Phase GEMM1: j=tid&127, half=tid>>7 handles 8 rows -> h into smem hs.
// Phase GEMM2: drug blocks compute t_ddi|t_dpi (dual 64); prot blocks t_ppi.
// Blocks [0,nbd) -> drug (rel0); [nbd,..) -> protein (rels 1+2).

__global__ void __launch_bounds__(256, 3)
k_l12(const float* __restrict__ xd, const float* __restrict__ xp,
      const float* __restrict__ W1_ddi, const float* __restrict__ b1_ddi,
      const float* __restrict__ W1_dpi, const float* __restrict__ b1_dpi,
      const float* __restrict__ W1_ppi, const float* __restrict__ b1_ppi,
      const float* __restrict__ W2_ddi, const float* __restrict__ W2_dpi,
      const float* __restrict__ W2_ppi,
      float* __restrict__ t_ddi, float* __restrict__ t_dpi,
      float* __restrict__ t_ppi,
      int nd, int np, int nbd) {
    __shared__ float2 xs1[16][64];
    __shared__ float2 xs2[16][64];
    __shared__ __align__(16) float hs[16][128];
    int tid = threadIdx.x, wid = tid >> 5, lane = tid & 31;
    bool drug = (int)blockIdx.x < nbd;
    int row0 = (drug ? blockIdx.x : blockIdx.x - nbd) * 16;
    int n = drug ? nd : np;

    int r0 = wid * 2, r1 = r0 + 1;
    int node0 = row0 + r0, node1 = row0 + r1;

    // ---- Phase G ----
    if (drug) {
        int b0, d0, b1, d1;
        node_range(g_rowptr[0], node0, n, b0, d0);
        node_range(g_rowptr[0], node1, n, b1, d1);
        float4 m0, m1;
        gpair128(g_esrc[0], xd, b0, d0, b1, d1, lane, m0, m1);
        xs1[r0][2 * lane]     = make_float2(m0.x, m0.y);
        xs1[r0][2 * lane + 1] = make_float2(m0.z, m0.w);
        xs1[r1][2 * lane]     = make_float2(m1.x, m1.y);
        xs1[r1][2 * lane + 1] = make_float2(m1.z, m1.w);
    } else {
        int b0, d0, b1, d1;
        node_range(g_rowptr[1], node0, n, b0, d0);
        node_range(g_rowptr[1], node1, n, b1, d1);
        float4 m0, m1;
        gpair128(g_esrc[1], xd, b0, d0, b1, d1, lane, m0, m1);
        xs1[r0][2 * lane]     = make_float2(m0.x, m0.y);
        xs1[r0][2 * lane + 1] = make_float2(m0.z, m0.w);
        xs1[r1][2 * lane]     = make_float2(m1.x, m1.y);
        xs1[r1][2 * lane + 1] = make_float2(m1.z, m1.w);

        node_range(g_rowptr[2], node0, n, b0, d0);
        node_range(g_rowptr[2], node1, n, b1, d1);
        gpair128(g_esrc[2], xp, b0, d0, b1, d1, lane, m0, m1);
        xs2[r0][2 * lane]     = make_float2(m0.x, m0.y);
        xs2[r0][2 * lane + 1] = make_float2(m0.z, m0.w);
        xs2[r1][2 * lane]     = make_float2(m1.x, m1.y);
        xs2[r1][2 * lane + 1] = make_float2(m1.z, m1.w);
    }
    __syncthreads();

    // ---- Phase GEMM1 -> hs ----
    {
        int j = tid & 127;
        int half = tid >> 7;
        int rbase = half * 8;
        ull acc[8];
#pragma unroll
        for (int p = 0; p < 8; p++) acc[p] = 0ull;

        if (drug) {
            for (int kk = 0; kk < 64; kk++) {
                ull wv = pack2(__ldg(W1_ddi + (2 * kk) * 128 + j),
                               __ldg(W1_ddi + (2 * kk + 1) * 128 + j));
#pragma unroll
                for (int p = 0; p < 8; p++)
                    acc[p] = ffma2(*reinterpret_cast<const ull*>(&xs1[rbase + p][kk]), wv, acc[p]);
            }
            float bb = __ldg(b1_ddi + j);
#pragma unroll
            for (int p = 0; p < 8; p++) {
                float lo, hi;
                unpack2(acc[p], lo, hi);
                hs[rbase + p][j] = lo + hi + bb;
            }
        } else {
            for (int kk = 0; kk < 64; kk++) {
                ull wv1 = pack2(__ldg(W1_dpi + (2 * kk) * 128 + j),
                                __ldg(W1_dpi + (2 * kk + 1) * 128 + j));
                ull wv2 = pack2(__ldg(W1_ppi + (2 * kk) * 128 + j),
                                __ldg(W1_ppi + (2 * kk + 1) * 128 + j));
#pragma unroll
                for (int p = 0; p < 8; p++) {
                    acc[p] = ffma2(*reinterpret_cast<const ull*>(&xs1[rbase + p][kk]), wv1, acc[p]);
                    acc[p] = ffma2(*reinterpret_cast<const ull*>(&xs2[rbase + p][kk]), wv2, acc[p]);
                }
            }
            float bb = __ldg(b1_dpi + j) + __ldg(b1_ppi + j);
#pragma unroll
            for (int p = 0; p < 8; p++) {
                float lo, hi;
                unpack2(acc[p], lo, hi);
                hs[rbase + p][j] = lo + hi + bb;
            }
        }
    }
    __syncthreads();

    // ---- Phase GEMM2 (from smem hs) ----
    if (drug) {
        int c = tid & 63;
        int sel = (tid >> 6) & 1;
        int rbase = (tid >> 7) * 8;
        const float* W = sel ? W2_dpi : W2_ddi;
        float* o = sel ? t_dpi : t_ddi;
        ull acc[8];
#pragma unroll
        for (int p = 0; p < 8; p++) acc[p] = 0ull;
        for (int kk = 0; kk < 64; kk++) {
            ull wv = pack2(__ldg(W + (2 * kk) * 64 + c),
                           __ldg(W + (2 * kk + 1) * 64 + c));
#pragma unroll
            for (int p = 0; p < 8; p++)
                acc[p] = ffma2(*reinterpret_cast<const ull*>(&hs[rbase + p][2 * kk]), wv, acc[p]);
        }
#pragma unroll
        for (int p = 0; p < 8; p++) {
            float lo, hi;
            unpack2(acc[p], lo, hi);
            int r = row0 + rbase + p;
            if (r < nd) o[(size_t)r * 64 + c] = lo + hi;
        }
    } else {
        int c = tid & 63;
        int rbase = (tid >> 6) * 4;
        ull acc[4];
#pragma unroll
        for (int p = 0; p < 4; p++) acc[p] = 0ull;
        for (int kk = 0; kk < 64; kk++) {
            ull wv = pack2(__ldg(W2_ppi + (2 * kk) * 64 + c),
                           __ldg(W2_ppi + (2 * kk + 1) * 64 + c));
#pragma unroll
            for (int p = 0; p < 4; p++)
                acc[p] = ffma2(*reinterpret_cast<const ull*>(&hs[rbase + p][2 * kk]), wv, acc[p]);
        }
#pragma unroll
        for (int p = 0; p < 4; p++) {
            float lo, hi;
            unpack2(acc[p], lo, hi);
            int r = row0 + rbase + p;
            if (r < np) t_ppi[(size_t)r * 64 + c] = lo + hi;
        }
    }
}

// ---------------- layer-2 gather + bias + concat (4 nodes/warp) ----------------

__global__ void __launch_bounds__(256)
k_out(const float* __restrict__ t_ddi, const float* __restrict__ t_dpi,
      const float* __restrict__ t_ppi,
      const float* __restrict__ b2_ddi, const float* __restrict__ b2_dpi,
      const float* __restrict__ b2_ppi,
      float* __restrict__ out, int nd, int np, int wd) {
    int gw = blockIdx.x * 8 + (threadIdx.x >> 5);
    int lane = threadIdx.x & 31;
    if (gw < wd) {
        int base = gw * 4;
        int b[4], d[4];
#pragma unroll
        for (int q = 0; q < 4; q++) node_range(g_rowptr[0], base + q, nd, b[q], d[q]);
        float2 m[4];
        gquad64(g_esrc[0], t_ddi, b, d, lane, m);
        float2 bb = __ldg(reinterpret_cast<const float2*>(b2_ddi) + lane);
#pragma unroll
        for (int q = 0; q < 4; q++) {
            int node = base + q;
            if (node < nd)
                *(reinterpret_cast<float2*>(out + (size_t)node * 64) + lane) =
                    make_float2(m[q].x + bb.x, m[q].y + bb.y);
        }
    } else {
        int base = (gw - wd) * 4;
        int b[4], d[4];
#pragma unroll
        for (int q = 0; q < 4; q++) node_range(g_rowptr[1], base + q, np, b[q], d[q]);
        float2 ma[4];
        gquad64(g_esrc[1], t_dpi, b, d, lane, ma);
#pragma unroll
        for (int q = 0; q < 4; q++) node_range(g_rowptr[2], base + q, np, b[q], d[q]);
        float2 mb[4];
        gquad64(g_esrc[2], t_ppi, b, d, lane, mb);
        float2 ba = __ldg(reinterpret_cast<const float2*>(b2_dpi) + lane);
        float2 bc = __ldg(reinterpret_cast<const float2*>(b2_ppi) + lane);
        float bx = ba.x + bc.x, by = ba.y + bc.y;
#pragma unroll
        for (int q = 0; q < 4; q++) {
            int node = base + q;
            if (node < np)
                *(reinterpret_cast<float2*>(out + (size_t)(nd + node) * 64) + lane) =
                    make_float2(ma[q].x + mb[q].x + bx, ma[q].y + mb[q].y + by);
        }
    }
}

// ---------------- host launcher ----------------

static float* fs_ptr() {
    static float* p = nullptr;
    if (!p) cudaGetSymbolAddress((void**)&p, g_fs);
    return p;
}

static inline int cdiv(long long a, long long b) { return (int)((a + b - 1) / b); }

extern "C" void kernel_launch(void* const* d_in, const int* in_sizes, int n_in,
                              void* d_out, int out_size) {
    const float* x_drug = (const float*)d_in[0];
    const float* x_prot = (const float*)d_in[1];
    const int* src_ddi = (const int*)d_in[2];
    const int* dst_ddi = (const int*)d_in[3];
    const int* src_dpi = (const int*)d_in[4];
    const int* dst_dpi = (const int*)d_in[5];
    const int* src_ppi = (const int*)d_in[6];
    const int* dst_ppi = (const int*)d_in[7];
    const float* W1_ddi = (const float*)d_in[8];
    const float* b1_ddi = (const float*)d_in[9];
    const float* W1_dpi = (const float*)d_in[10];
    const float* b1_dpi = (const float*)d_in[11];
    const float* W1_ppi = (const float*)d_in[12];
    const float* b1_ppi = (const float*)d_in[13];
    const float* W2_ddi = (const float*)d_in[14];
    const float* b2_ddi = (const float*)d_in[15];
    const float* W2_dpi = (const float*)d_in[16];
    const float* b2_dpi = (const float*)d_in[17];
    const float* W2_ppi = (const float*)d_in[18];
    const float* b2_ppi = (const float*)d_in[19];
    float* out = (float*)d_out;

    int nd = in_sizes[0] / 128;
    int np = in_sizes[1] / 128;
    int ed = in_sizes[2];
    int ep = in_sizes[4];
    int eq = in_sizes[6];

    float* S = fs_ptr();
    float* t_ddi = S + F_T_DDI;
    float* t_dpi = S + F_T_DPI;
    float* t_ppi = S + F_T_PPI;

    // ---- CSR build ----
    k_zero_counts<<<cdiv(3 * (NMAX + 1), 256), 256>>>();
    int emax = ed > ep ? ed : ep;
    if (eq > emax) emax = eq;
    k_count<<<cdiv(emax, 256), 256>>>(dst_ddi, ed, dst_dpi, ep, dst_ppi, eq);

    int nmax = nd > np ? nd : np;
    int sblk = cdiv(nmax, SCAN_BLK);
    k_scan1<<<3 * sblk, 1024>>>(sblk, nd, np, np);
    k_scan2<<<1, 96>>>(sblk);
    k_scan3<<<cdiv(3 * NMAX, 256), 256>>>(sblk, nd, np, np);

    k_fill3<<<cdiv(emax, 256), 256>>>(src_ddi, dst_ddi, ed,
                                      src_dpi, dst_dpi, ep,
                                      src_ppi, dst_ppi, eq);

    // ---- fused layer-1 gather + GEMM1 + GEMM2 ----
    int nbd = cdiv(nd, 16), nbp = cdiv(np, 16);
    k_l12<<<nbd + nbp, 256>>>(x_drug, x_prot,
                              W1_ddi, b1_ddi, W1_dpi, b1_dpi, W1_ppi, b1_ppi,
                              W2_ddi, W2_dpi, W2_ppi,
                              t_ddi, t_dpi, t_ppi, nd, np, nbd);

    // ---- layer-2 gather + bias + concat ----
    int wd = cdiv(nd, 4), wp = cdiv(np, 4);
    k_out<<<cdiv(wd + wp, 8), 256>>>(t_ddi, t_dpi, t_ppi,
                                     b2_ddi, b2_dpi, b2_ppi, out, nd, np, wd);
}